// round 1
// baseline (speedup 1.0000x reference)
#include <cuda_runtime.h>

// ---------------- problem constants ----------------
#define TT 256
#define D1 512
#define HW1 (512*512)   // 262144
#define HW2 (256*256)   // 65536
#define HW4 (128*128)   // 16384
#define HW8 (64*64)     // 4096

// ---------------- device scratch (no allocations allowed) ----------------
__device__ float g_img2[(size_t)TT * HW2];   // 67 MB
__device__ float g_img4[(size_t)TT * HW4];   // 17 MB
__device__ float g_img8[(size_t)TT * HW8];   //  4 MB
__device__ float g_s[4 * TT];                // per-level row dots

// ---------------- zero the accumulators (graph-replay safe) ----------------
__global__ void zero_s_kernel() {
    g_s[threadIdx.x] = 0.0f;
}

// ---------------- fused avgpool: img -> img2, img4, img8 ----------------
// Each thread handles one 8x8 patch of the 512x512 image.
__global__ void pool_kernel(const float* __restrict__ x) {
    int gid = blockIdx.x * blockDim.x + threadIdx.x;   // t*4096 + p
    int t  = gid >> 12;
    int p  = gid & 4095;
    int ph = p >> 6;       // patch row 0..63
    int pw = p & 63;       // patch col 0..63

    const float* base = x + (size_t)t * HW1 + (size_t)(ph * 8) * D1 + pw * 8;

    float s2[4][4];
#pragma unroll
    for (int r2 = 0; r2 < 4; r2++) {
        float4 a0 = *(const float4*)(base + (size_t)(2 * r2) * D1);
        float4 b0 = *(const float4*)(base + (size_t)(2 * r2) * D1 + 4);
        float4 a1 = *(const float4*)(base + (size_t)(2 * r2 + 1) * D1);
        float4 b1 = *(const float4*)(base + (size_t)(2 * r2 + 1) * D1 + 4);
        s2[r2][0] = (a0.x + a0.y + a1.x + a1.y) * 0.25f;
        s2[r2][1] = (a0.z + a0.w + a1.z + a1.w) * 0.25f;
        s2[r2][2] = (b0.x + b0.y + b1.x + b1.y) * 0.25f;
        s2[r2][3] = (b0.z + b0.w + b1.z + b1.w) * 0.25f;
    }

    // img2: rows ph*4 .. ph*4+3, cols pw*4 .. pw*4+3 (float4 stores)
    float* o2 = g_img2 + (size_t)t * HW2;
#pragma unroll
    for (int r2 = 0; r2 < 4; r2++) {
        float4 v = make_float4(s2[r2][0], s2[r2][1], s2[r2][2], s2[r2][3]);
        *(float4*)(o2 + (size_t)(ph * 4 + r2) * 256 + pw * 4) = v;
    }

    float s4[2][2];
#pragma unroll
    for (int r4 = 0; r4 < 2; r4++)
#pragma unroll
        for (int c4 = 0; c4 < 2; c4++)
            s4[r4][c4] = (s2[2*r4][2*c4] + s2[2*r4][2*c4+1]
                        + s2[2*r4+1][2*c4] + s2[2*r4+1][2*c4+1]) * 0.25f;

    float* o4 = g_img4 + (size_t)t * HW4;
#pragma unroll
    for (int r4 = 0; r4 < 2; r4++) {
        float2 v = make_float2(s4[r4][0], s4[r4][1]);
        *(float2*)(o4 + (size_t)(ph * 2 + r4) * 128 + pw * 2) = v;
    }

    g_img8[(size_t)t * HW8 + (size_t)ph * 64 + pw] =
        (s4[0][0] + s4[0][1] + s4[1][0] + s4[1][1]) * 0.25f;
}

// ---------------- fused affine_grid + grid_sample + dot with Wk ----------------
// One thread per output pixel. dim = H = W (square), logdim = log2(dim).
__global__ void sample_dot_kernel(const float* __restrict__ img,
                                  const float* __restrict__ theta,
                                  const float* __restrict__ Wk,
                                  float* __restrict__ xreg,
                                  int level, int dim, int logdim) {
    int t   = blockIdx.y;
    int idx = blockIdx.x * blockDim.x + threadIdx.x;
    int w   = idx & (dim - 1);
    int h   = idx >> logdim;

    float inv = 2.0f / (float)dim;
    float xn = ((float)w + 0.5f) * inv - 1.0f;
    float yn = ((float)h + 0.5f) * inv - 1.0f;

    const float* th = theta + t * 6;
    float gx = __ldg(th + 0) * xn + __ldg(th + 1) * yn + __ldg(th + 2);
    float gy = __ldg(th + 3) * xn + __ldg(th + 4) * yn + __ldg(th + 5);

    // ix = ((gx+1)*W - 1) * 0.5 = (gx+1)*(W/2) - 0.5
    float half = 0.5f * (float)dim;
    float ix = fmaf(gx + 1.0f, half, -0.5f);
    float iy = fmaf(gy + 1.0f, half, -0.5f);

    float fx = floorf(ix), fy = floorf(iy);
    int x0 = (int)fx, y0 = (int)fy;
    float wx = ix - fx, wy = iy - fy;

    const float* base = img + (size_t)t * dim * dim;
    float v00 = 0.f, v01 = 0.f, v10 = 0.f, v11 = 0.f;
    bool x0v = (x0 >= 0) & (x0 < dim);
    bool x1v = (x0 + 1 >= 0) & (x0 + 1 < dim);
    bool y0v = (y0 >= 0) & (y0 < dim);
    bool y1v = (y0 + 1 >= 0) & (y0 + 1 < dim);
    if (y0v) {
        const float* r = base + (size_t)y0 * dim;
        if (x0v) v00 = __ldg(r + x0);
        if (x1v) v01 = __ldg(r + x0 + 1);
    }
    if (y1v) {
        const float* r = base + (size_t)(y0 + 1) * dim;
        if (x0v) v10 = __ldg(r + x0);
        if (x1v) v11 = __ldg(r + x0 + 1);
    }
    float val = (v00 * (1.0f - wx) + v01 * wx) * (1.0f - wy)
              + (v10 * (1.0f - wx) + v11 * wx) * wy;

    xreg[(size_t)t * dim * dim + idx] = val;

    // contribution to s[t] = sum_i x_reg[t,i] * Wk[i]
    float c = val * __ldg(Wk + idx);
#pragma unroll
    for (int o = 16; o; o >>= 1)
        c += __shfl_down_sync(0xffffffffu, c, o);

    __shared__ float sm[8];
    int lane = threadIdx.x & 31;
    int wrp  = threadIdx.x >> 5;
    if (lane == 0) sm[wrp] = c;
    __syncthreads();
    if (wrp == 0) {
        float v = (lane < 8) ? sm[lane] : 0.0f;
#pragma unroll
        for (int o = 4; o; o >>= 1)
            v += __shfl_down_sync(0xffffffffu, v, o);
        if (lane == 0) atomicAdd(&g_s[level * TT + t], v);
    }
}

// ---------------- rank-1 outer product: L[t,:] = s[t] * Wk ----------------
__global__ void outer_kernel(const float* __restrict__ Wk,
                             float* __restrict__ L,
                             int level, int hw4) {
    int t = blockIdx.y;
    int i = blockIdx.x * blockDim.x + threadIdx.x;   // float4 index
    float sv = g_s[level * TT + t];
    float4 wv = __ldg((const float4*)Wk + i);
    float4 o = make_float4(sv * wv.x, sv * wv.y, sv * wv.z, sv * wv.w);
    *((float4*)L + (size_t)t * hw4 + i) = o;
}

extern "C" void kernel_launch(void* const* d_in, const int* in_sizes, int n_in,
                              void* d_out, int out_size) {
    const float* x     = (const float*)d_in[0];
    const float* theta = (const float*)d_in[1];
    const float* W1    = (const float*)d_in[2];
    const float* W2    = (const float*)d_in[3];
    const float* W4    = (const float*)d_in[4];
    const float* W8    = (const float*)d_in[5];
    float* out = (float*)d_out;

    // output tuple layout: x_reg, L, x_reg2, L2, x_reg4, L4, x_reg8, L8
    size_t off = 0;
    float* xr1 = out + off; off += (size_t)TT * HW1;
    float* L1  = out + off; off += (size_t)TT * HW1;
    float* xr2 = out + off; off += (size_t)TT * HW2;
    float* L2  = out + off; off += (size_t)TT * HW2;
    float* xr4 = out + off; off += (size_t)TT * HW4;
    float* L4  = out + off; off += (size_t)TT * HW4;
    float* xr8 = out + off; off += (size_t)TT * HW8;
    float* L8  = out + off; off += (size_t)TT * HW8;

    void *p2, *p4, *p8;
    cudaGetSymbolAddress(&p2, g_img2);
    cudaGetSymbolAddress(&p4, g_img4);
    cudaGetSymbolAddress(&p8, g_img8);
    const float* i2 = (const float*)p2;
    const float* i4 = (const float*)p4;
    const float* i8 = (const float*)p8;

    zero_s_kernel<<<1, 4 * TT>>>();
    pool_kernel<<<(TT * 4096) / 256, 256>>>(x);

    sample_dot_kernel<<<dim3(HW1 / 256, TT), 256>>>(x,  theta, W1, xr1, 0, 512, 9);
    sample_dot_kernel<<<dim3(HW2 / 256, TT), 256>>>(i2, theta, W2, xr2, 1, 256, 8);
    sample_dot_kernel<<<dim3(HW4 / 256, TT), 256>>>(i4, theta, W4, xr4, 2, 128, 7);
    sample_dot_kernel<<<dim3(HW8 / 256, TT), 256>>>(i8, theta, W8, xr8, 3, 64, 6);

    outer_kernel<<<dim3(HW1 / 1024, TT), 256>>>(W1, L1, 0, HW1 / 4);
    outer_kernel<<<dim3(HW2 / 1024, TT), 256>>>(W2, L2, 1, HW2 / 4);
    outer_kernel<<<dim3(HW4 / 1024, TT), 256>>>(W4, L4, 2, HW4 / 4);
    outer_kernel<<<dim3(HW8 / 1024, TT), 256>>>(W8, L8, 3, HW8 / 4);
}

// round 2
// speedup vs baseline: 1.8107x; 1.8107x over previous
#include <cuda_runtime.h>

// ---------------- problem constants ----------------
#define TT 256
#define D1 512
#define HW1 (512*512)
#define HW2 (256*256)
#define HW4 (128*128)
#define HW8 (64*64)

// ---------------- device scratch (no allocations allowed) ----------------
__device__ float g_img2[(size_t)TT * HW2];
__device__ float g_img4[(size_t)TT * HW4];
__device__ float g_img8[(size_t)TT * HW8];
__device__ float g_s[4 * TT];

__global__ void zero_s_kernel() {
    g_s[threadIdx.x] = 0.0f;
}

// ---------------- fused avgpool: img -> img2, img4, img8 ----------------
__global__ void pool_kernel(const float* __restrict__ x) {
    int gid = blockIdx.x * blockDim.x + threadIdx.x;
    int t  = gid >> 12;
    int p  = gid & 4095;
    int ph = p >> 6;
    int pw = p & 63;

    const float* base = x + (size_t)t * HW1 + (size_t)(ph * 8) * D1 + pw * 8;

    float s2[4][4];
#pragma unroll
    for (int r2 = 0; r2 < 4; r2++) {
        float4 a0 = *(const float4*)(base + (size_t)(2 * r2) * D1);
        float4 b0 = *(const float4*)(base + (size_t)(2 * r2) * D1 + 4);
        float4 a1 = *(const float4*)(base + (size_t)(2 * r2 + 1) * D1);
        float4 b1 = *(const float4*)(base + (size_t)(2 * r2 + 1) * D1 + 4);
        s2[r2][0] = (a0.x + a0.y + a1.x + a1.y) * 0.25f;
        s2[r2][1] = (a0.z + a0.w + a1.z + a1.w) * 0.25f;
        s2[r2][2] = (b0.x + b0.y + b1.x + b1.y) * 0.25f;
        s2[r2][3] = (b0.z + b0.w + b1.z + b1.w) * 0.25f;
    }

    float* o2 = g_img2 + (size_t)t * HW2;
#pragma unroll
    for (int r2 = 0; r2 < 4; r2++) {
        float4 v = make_float4(s2[r2][0], s2[r2][1], s2[r2][2], s2[r2][3]);
        *(float4*)(o2 + (size_t)(ph * 4 + r2) * 256 + pw * 4) = v;
    }

    float s4[2][2];
#pragma unroll
    for (int r4 = 0; r4 < 2; r4++)
#pragma unroll
        for (int c4 = 0; c4 < 2; c4++)
            s4[r4][c4] = (s2[2*r4][2*c4] + s2[2*r4][2*c4+1]
                        + s2[2*r4+1][2*c4] + s2[2*r4+1][2*c4+1]) * 0.25f;

    float* o4 = g_img4 + (size_t)t * HW4;
#pragma unroll
    for (int r4 = 0; r4 < 2; r4++) {
        float2 v = make_float2(s4[r4][0], s4[r4][1]);
        *(float2*)(o4 + (size_t)(ph * 2 + r4) * 128 + pw * 2) = v;
    }

    g_img8[(size_t)t * HW8 + (size_t)ph * 64 + pw] =
        (s4[0][0] + s4[0][1] + s4[1][0] + s4[1][1]) * 0.25f;
}

// ---------------- fused affine_grid + grid_sample + dot with Wk ----------------
// 4 pixels per thread along w; affine coords computed incrementally
// (d(ix)/dw = th00, d(iy)/dw = th10 exactly, in pixel units).
template<int DIM>
__global__ void sample_dot_kernel(const float* __restrict__ img,
                                  const float* __restrict__ theta,
                                  const float* __restrict__ Wk,
                                  float* __restrict__ xreg,
                                  int level) {
    constexpr int LOG = (DIM == 512) ? 9 : (DIM == 256) ? 8 : (DIM == 128) ? 7 : 6;
    const int t    = blockIdx.y;
    const int idx4 = blockIdx.x * blockDim.x + threadIdx.x;   // float4 index
    const int idx  = idx4 << 2;
    const int w0   = idx & (DIM - 1);
    const int h    = idx >> LOG;

    const float* th = theta + t * 6;
    const float th0 = __ldg(th + 0), th1 = __ldg(th + 1), th2 = __ldg(th + 2);
    const float th3 = __ldg(th + 3), th4 = __ldg(th + 4), th5 = __ldg(th + 5);

    constexpr float inv  = 2.0f / (float)DIM;
    constexpr float half = 0.5f * (float)DIM;
    const float yn  = ((float)h  + 0.5f) * inv - 1.0f;
    const float xn0 = ((float)w0 + 0.5f) * inv - 1.0f;
    const float gx0 = fmaf(th0, xn0, fmaf(th1, yn, th2));
    const float gy0 = fmaf(th3, xn0, fmaf(th4, yn, th5));
    const float ix0 = fmaf(gx0 + 1.0f, half, -0.5f);
    const float iy0 = fmaf(gy0 + 1.0f, half, -0.5f);

    const float* base = img + (size_t)t * (DIM * DIM);
    const float4 wv = __ldg((const float4*)Wk + idx4);
    const float wk[4] = {wv.x, wv.y, wv.z, wv.w};

    float out[4];
    float c = 0.0f;
#pragma unroll
    for (int j = 0; j < 4; j++) {
        const float ix = fmaf((float)j, th0, ix0);
        const float iy = fmaf((float)j, th3, iy0);
        const float fx = floorf(ix), fy = floorf(iy);
        const int x0 = (int)fx, y0 = (int)fy;
        const float wx = ix - fx, wy = iy - fy;

        const bool x0v = (unsigned)x0       < (unsigned)DIM;
        const bool x1v = (unsigned)(x0 + 1) < (unsigned)DIM;
        const bool y0v = (unsigned)y0       < (unsigned)DIM;
        const bool y1v = (unsigned)(y0 + 1) < (unsigned)DIM;

        const int x0c = min(max(x0, 0), DIM - 1);
        const int x1c = min(x0 + 1, DIM - 1);          // x0+1 >= 0 whenever x1v cares
        const int y0c = min(max(y0, 0), DIM - 1);
        const int y1c = min(max(y0 + 1, 0), DIM - 1);

        const float* r0 = base + (size_t)y0c * DIM;
        const float* r1 = base + (size_t)y1c * DIM;
        const float v00 = __ldg(r0 + x0c);
        const float v01 = __ldg(r0 + max(x1c, 0));
        const float v10 = __ldg(r1 + x0c);
        const float v11 = __ldg(r1 + max(x1c, 0));

        const float wx1 = x1v ? wx : 0.0f;
        const float wx0 = x0v ? (1.0f - wx) : 0.0f;
        const float wy1 = y1v ? wy : 0.0f;
        const float wy0 = y0v ? (1.0f - wy) : 0.0f;

        const float top = fmaf(v01, wx1, v00 * wx0);
        const float bot = fmaf(v11, wx1, v10 * wx0);
        const float val = fmaf(bot, wy1, top * wy0);
        out[j] = val;
        c = fmaf(val, wk[j], c);
    }

    *(float4*)(xreg + (size_t)t * (DIM * DIM) + idx) =
        make_float4(out[0], out[1], out[2], out[3]);

#pragma unroll
    for (int o = 16; o; o >>= 1)
        c += __shfl_down_sync(0xffffffffu, c, o);

    __shared__ float sm[8];
    const int lane = threadIdx.x & 31;
    const int wrp  = threadIdx.x >> 5;
    if (lane == 0) sm[wrp] = c;
    __syncthreads();
    if (wrp == 0) {
        float v = (lane < 8) ? sm[lane] : 0.0f;
#pragma unroll
        for (int o = 4; o; o >>= 1)
            v += __shfl_down_sync(0xffffffffu, v, o);
        if (lane == 0) atomicAdd(&g_s[level * TT + t], v);
    }
}

// ---------------- rank-1 outer product: L[t,:] = s[t] * Wk ----------------
__global__ void outer_kernel(const float* __restrict__ Wk,
                             float* __restrict__ L,
                             int level, int hw4) {
    int t = blockIdx.y;
    int i = blockIdx.x * blockDim.x + threadIdx.x;
    float sv = g_s[level * TT + t];
    float4 wv = __ldg((const float4*)Wk + i);
    float4 o = make_float4(sv * wv.x, sv * wv.y, sv * wv.z, sv * wv.w);
    *((float4*)L + (size_t)t * hw4 + i) = o;
}

extern "C" void kernel_launch(void* const* d_in, const int* in_sizes, int n_in,
                              void* d_out, int out_size) {
    const float* x     = (const float*)d_in[0];
    const float* theta = (const float*)d_in[1];
    const float* W1    = (const float*)d_in[2];
    const float* W2    = (const float*)d_in[3];
    const float* W4    = (const float*)d_in[4];
    const float* W8    = (const float*)d_in[5];
    float* out = (float*)d_out;

    size_t off = 0;
    float* xr1 = out + off; off += (size_t)TT * HW1;
    float* L1  = out + off; off += (size_t)TT * HW1;
    float* xr2 = out + off; off += (size_t)TT * HW2;
    float* L2  = out + off; off += (size_t)TT * HW2;
    float* xr4 = out + off; off += (size_t)TT * HW4;
    float* L4  = out + off; off += (size_t)TT * HW4;
    float* xr8 = out + off; off += (size_t)TT * HW8;
    float* L8  = out + off; off += (size_t)TT * HW8;

    void *p2, *p4, *p8;
    cudaGetSymbolAddress(&p2, g_img2);
    cudaGetSymbolAddress(&p4, g_img4);
    cudaGetSymbolAddress(&p8, g_img8);
    const float* i2 = (const float*)p2;
    const float* i4 = (const float*)p4;
    const float* i8 = (const float*)p8;

    zero_s_kernel<<<1, 4 * TT>>>();
    pool_kernel<<<(TT * 4096) / 256, 256>>>(x);

    sample_dot_kernel<512><<<dim3(HW1 / 1024, TT), 256>>>(x,  theta, W1, xr1, 0);
    sample_dot_kernel<256><<<dim3(HW2 / 1024, TT), 256>>>(i2, theta, W2, xr2, 1);
    sample_dot_kernel<128><<<dim3(HW4 / 1024, TT), 256>>>(i4, theta, W4, xr4, 2);
    sample_dot_kernel< 64><<<dim3(HW8 / 1024, TT), 256>>>(i8, theta, W8, xr8, 3);

    outer_kernel<<<dim3(HW1 / 1024, TT), 256>>>(W1, L1, 0, HW1 / 4);
    outer_kernel<<<dim3(HW2 / 1024, TT), 256>>>(W2, L2, 1, HW2 / 4);
    outer_kernel<<<dim3(HW4 / 1024, TT), 256>>>(W4, L4, 2, HW4 / 4);
    outer_kernel<<<dim3(HW8 / 1024, TT), 256>>>(W8, L8, 3, HW8 / 4);
}

// round 3
// speedup vs baseline: 1.9110x; 1.0554x over previous
#include <cuda_runtime.h>

// ---------------- problem constants ----------------
#define TT 256
#define D1 512
#define HW1 (512*512)
#define HW2 (256*256)
#define HW4 (128*128)
#define HW8 (64*64)

// ---------------- device scratch (no allocations allowed) ----------------
__device__ float g_img2[(size_t)TT * HW2];
__device__ float g_img4[(size_t)TT * HW4];
__device__ float g_img8[(size_t)TT * HW8];
__device__ float g_s[4 * TT];

__device__ __forceinline__ void st_cs(float* p, float v) {
    asm volatile("st.global.cs.f32 [%0], %1;" :: "l"(p), "f"(v) : "memory");
}
__device__ __forceinline__ void st_cs4(float* p, float4 v) {
    asm volatile("st.global.cs.v4.f32 [%0], {%1,%2,%3,%4};"
                 :: "l"(p), "f"(v.x), "f"(v.y), "f"(v.z), "f"(v.w) : "memory");
}

__global__ void zero_s_kernel() {
    g_s[threadIdx.x] = 0.0f;
}

// ---------------- fused avgpool: img -> img2, img4, img8 ----------------
__global__ void pool_kernel(const float* __restrict__ x) {
    int gid = blockIdx.x * blockDim.x + threadIdx.x;
    int t  = gid >> 12;
    int p  = gid & 4095;
    int ph = p >> 6;
    int pw = p & 63;

    const float* base = x + (size_t)t * HW1 + (size_t)(ph * 8) * D1 + pw * 8;

    float s2[4][4];
#pragma unroll
    for (int r2 = 0; r2 < 4; r2++) {
        float4 a0 = *(const float4*)(base + (size_t)(2 * r2) * D1);
        float4 b0 = *(const float4*)(base + (size_t)(2 * r2) * D1 + 4);
        float4 a1 = *(const float4*)(base + (size_t)(2 * r2 + 1) * D1);
        float4 b1 = *(const float4*)(base + (size_t)(2 * r2 + 1) * D1 + 4);
        s2[r2][0] = (a0.x + a0.y + a1.x + a1.y) * 0.25f;
        s2[r2][1] = (a0.z + a0.w + a1.z + a1.w) * 0.25f;
        s2[r2][2] = (b0.x + b0.y + b1.x + b1.y) * 0.25f;
        s2[r2][3] = (b0.z + b0.w + b1.z + b1.w) * 0.25f;
    }

    float* o2 = g_img2 + (size_t)t * HW2;
#pragma unroll
    for (int r2 = 0; r2 < 4; r2++) {
        float4 v = make_float4(s2[r2][0], s2[r2][1], s2[r2][2], s2[r2][3]);
        *(float4*)(o2 + (size_t)(ph * 4 + r2) * 256 + pw * 4) = v;
    }

    float s4[2][2];
#pragma unroll
    for (int r4 = 0; r4 < 2; r4++)
#pragma unroll
        for (int c4 = 0; c4 < 2; c4++)
            s4[r4][c4] = (s2[2*r4][2*c4] + s2[2*r4][2*c4+1]
                        + s2[2*r4+1][2*c4] + s2[2*r4+1][2*c4+1]) * 0.25f;

    float* o4 = g_img4 + (size_t)t * HW4;
#pragma unroll
    for (int r4 = 0; r4 < 2; r4++) {
        float2 v = make_float2(s4[r4][0], s4[r4][1]);
        *(float2*)(o4 + (size_t)(ph * 2 + r4) * 128 + pw * 2) = v;
    }

    g_img8[(size_t)t * HW8 + (size_t)ph * 64 + pw] =
        (s4[0][0] + s4[0][1] + s4[1][0] + s4[1][1]) * 0.25f;
}

// ---------------- fused affine_grid + grid_sample + dot with Wk ----------------
// Each thread owns a 4-high column of pixels (h0..h0+3, w); lanes are
// consecutive in w, so every gather is warp-contiguous (theta ~= identity).
// d(ix)/dh = th1, d(iy)/dh = th4 in pixel units.
template<int DIM>
__global__ void sample_dot_kernel(const float* __restrict__ img,
                                  const float* __restrict__ theta,
                                  const float* __restrict__ Wk,
                                  float* __restrict__ xreg,
                                  int level) {
    constexpr int LOG = (DIM == 512) ? 9 : (DIM == 256) ? 8 : (DIM == 128) ? 7 : 6;
    const int t   = blockIdx.y;
    const int tid = blockIdx.x * blockDim.x + threadIdx.x;   // 0..HW/4-1
    const int w   = tid & (DIM - 1);
    const int h0  = (tid >> LOG) << 2;

    const float* th = theta + t * 6;
    const float th0 = __ldg(th + 0), th1 = __ldg(th + 1), th2 = __ldg(th + 2);
    const float th3 = __ldg(th + 3), th4 = __ldg(th + 4), th5 = __ldg(th + 5);

    constexpr float inv  = 2.0f / (float)DIM;
    constexpr float half = 0.5f * (float)DIM;
    const float xn  = ((float)w  + 0.5f) * inv - 1.0f;
    const float yn0 = ((float)h0 + 0.5f) * inv - 1.0f;
    const float gx0 = fmaf(th0, xn, fmaf(th1, yn0, th2));
    const float gy0 = fmaf(th3, xn, fmaf(th4, yn0, th5));
    const float ix0 = fmaf(gx0 + 1.0f, half, -0.5f);
    const float iy0 = fmaf(gy0 + 1.0f, half, -0.5f);
    const float ix3 = fmaf(3.0f, th1, ix0);
    const float iy3 = fmaf(3.0f, th4, iy0);

    const float* base = img + (size_t)t * (DIM * DIM);
    const size_t obase = (size_t)t * (DIM * DIM) + (size_t)h0 * DIM + w;

    // interior test over the whole 4-pixel column (coords monotonic in j)
    const bool interior =
        fminf(ix0, ix3) >= 0.0f && fmaxf(ix0, ix3) < (float)(DIM - 1) &&
        fminf(iy0, iy3) >= 0.0f && fmaxf(iy0, iy3) < (float)(DIM - 1);

    float c = 0.0f;
    if (interior) {
#pragma unroll
        for (int j = 0; j < 4; j++) {
            const float ix = fmaf((float)j, th1, ix0);
            const float iy = fmaf((float)j, th4, iy0);
            const float fx = floorf(ix), fy = floorf(iy);
            const int x0 = (int)fx, y0 = (int)fy;
            const float wx = ix - fx, wy = iy - fy;

            const float* r0 = base + (size_t)y0 * DIM + x0;
            const float* r1 = r0 + DIM;
            const float v00 = __ldg(r0);
            const float v01 = __ldg(r0 + 1);
            const float v10 = __ldg(r1);
            const float v11 = __ldg(r1 + 1);

            const float top = fmaf(v01, wx, v00 * (1.0f - wx));
            const float bot = fmaf(v11, wx, v10 * (1.0f - wx));
            const float val = fmaf(bot, wy, top * (1.0f - wy));
            st_cs(xreg + obase + (size_t)j * DIM, val);
            c = fmaf(val, __ldg(Wk + (h0 + j) * DIM + w), c);
        }
    } else {
#pragma unroll
        for (int j = 0; j < 4; j++) {
            const float ix = fmaf((float)j, th1, ix0);
            const float iy = fmaf((float)j, th4, iy0);
            const float fx = floorf(ix), fy = floorf(iy);
            const int x0 = (int)fx, y0 = (int)fy;
            const float wx = ix - fx, wy = iy - fy;

            const bool x0v = (unsigned)x0       < (unsigned)DIM;
            const bool x1v = (unsigned)(x0 + 1) < (unsigned)DIM;
            const bool y0v = (unsigned)y0       < (unsigned)DIM;
            const bool y1v = (unsigned)(y0 + 1) < (unsigned)DIM;

            const int x0c = min(max(x0, 0), DIM - 1);
            const int x1c = min(max(x0 + 1, 0), DIM - 1);
            const int y0c = min(max(y0, 0), DIM - 1);
            const int y1c = min(max(y0 + 1, 0), DIM - 1);

            const float* r0 = base + (size_t)y0c * DIM;
            const float* r1 = base + (size_t)y1c * DIM;
            const float v00 = __ldg(r0 + x0c);
            const float v01 = __ldg(r0 + x1c);
            const float v10 = __ldg(r1 + x0c);
            const float v11 = __ldg(r1 + x1c);

            const float wx1 = x1v ? wx : 0.0f;
            const float wx0 = x0v ? (1.0f - wx) : 0.0f;
            const float wy1 = y1v ? wy : 0.0f;
            const float wy0 = y0v ? (1.0f - wy) : 0.0f;

            const float top = fmaf(v01, wx1, v00 * wx0);
            const float bot = fmaf(v11, wx1, v10 * wx0);
            const float val = fmaf(bot, wy1, top * wy0);
            st_cs(xreg + obase + (size_t)j * DIM, val);
            c = fmaf(val, __ldg(Wk + (h0 + j) * DIM + w), c);
        }
    }

#pragma unroll
    for (int o = 16; o; o >>= 1)
        c += __shfl_down_sync(0xffffffffu, c, o);

    __shared__ float sm[8];
    const int lane = threadIdx.x & 31;
    const int wrp  = threadIdx.x >> 5;
    if (lane == 0) sm[wrp] = c;
    __syncthreads();
    if (wrp == 0) {
        float v = (lane < 8) ? sm[lane] : 0.0f;
#pragma unroll
        for (int o = 4; o; o >>= 1)
            v += __shfl_down_sync(0xffffffffu, v, o);
        if (lane == 0) atomicAdd(&g_s[level * TT + t], v);
    }
}

// ---------------- rank-1 outer product: L[t,:] = s[t] * Wk ----------------
__global__ void outer_kernel(const float* __restrict__ Wk,
                             float* __restrict__ L,
                             int level, int hw4) {
    int t = blockIdx.y;
    int i = blockIdx.x * blockDim.x + threadIdx.x;
    float sv = g_s[level * TT + t];
    float4 wv = __ldg((const float4*)Wk + i);
    float4 o = make_float4(sv * wv.x, sv * wv.y, sv * wv.z, sv * wv.w);
    st_cs4((float*)((float4*)L + (size_t)t * hw4 + i), o);
}

extern "C" void kernel_launch(void* const* d_in, const int* in_sizes, int n_in,
                              void* d_out, int out_size) {
    const float* x     = (const float*)d_in[0];
    const float* theta = (const float*)d_in[1];
    const float* W1    = (const float*)d_in[2];
    const float* W2    = (const float*)d_in[3];
    const float* W4    = (const float*)d_in[4];
    const float* W8    = (const float*)d_in[5];
    float* out = (float*)d_out;

    size_t off = 0;
    float* xr1 = out + off; off += (size_t)TT * HW1;
    float* L1  = out + off; off += (size_t)TT * HW1;
    float* xr2 = out + off; off += (size_t)TT * HW2;
    float* L2  = out + off; off += (size_t)TT * HW2;
    float* xr4 = out + off; off += (size_t)TT * HW4;
    float* L4  = out + off; off += (size_t)TT * HW4;
    float* xr8 = out + off; off += (size_t)TT * HW8;
    float* L8  = out + off; off += (size_t)TT * HW8;

    void *p2, *p4, *p8;
    cudaGetSymbolAddress(&p2, g_img2);
    cudaGetSymbolAddress(&p4, g_img4);
    cudaGetSymbolAddress(&p8, g_img8);
    const float* i2 = (const float*)p2;
    const float* i4 = (const float*)p4;
    const float* i8 = (const float*)p8;

    zero_s_kernel<<<1, 4 * TT>>>();
    pool_kernel<<<(TT * 4096) / 256, 256>>>(x);

    sample_dot_kernel<512><<<dim3(HW1 / 1024, TT), 256>>>(x,  theta, W1, xr1, 0);
    sample_dot_kernel<256><<<dim3(HW2 / 1024, TT), 256>>>(i2, theta, W2, xr2, 1);
    sample_dot_kernel<128><<<dim3(HW4 / 1024, TT), 256>>>(i4, theta, W4, xr4, 2);
    sample_dot_kernel< 64><<<dim3(HW8 / 1024, TT), 256>>>(i8, theta, W8, xr8, 3);

    outer_kernel<<<dim3(HW1 / 1024, TT), 256>>>(W1, L1, 0, HW1 / 4);
    outer_kernel<<<dim3(HW2 / 1024, TT), 256>>>(W2, L2, 1, HW2 / 4);
    outer_kernel<<<dim3(HW4 / 1024, TT), 256>>>(W4, L4, 2, HW4 / 4);
    outer_kernel<<<dim3(HW8 / 1024, TT), 256>>>(W8, L8, 3, HW8 / 4);
}

// round 4
// speedup vs baseline: 1.9930x; 1.0429x over previous
#include <cuda_runtime.h>

// ---------------- problem constants ----------------
#define TT 256
#define D1 512
#define HW1 (512*512)
#define HW2 (256*256)
#define HW4 (128*128)
#define HW8 (64*64)

// ---------------- device scratch (no allocations allowed) ----------------
__device__ float g_img2[(size_t)TT * HW2];
__device__ float g_img4[(size_t)TT * HW4];
__device__ float g_img8[(size_t)TT * HW8];
__device__ float g_s[4 * TT];

__device__ __forceinline__ void st_cs(float* p, float v) {
    asm volatile("st.global.cs.f32 [%0], %1;" :: "l"(p), "f"(v) : "memory");
}
__device__ __forceinline__ void st_cs4(float* p, float4 v) {
    asm volatile("st.global.cs.v4.f32 [%0], {%1,%2,%3,%4};"
                 :: "l"(p), "f"(v.x), "f"(v.y), "f"(v.z), "f"(v.w) : "memory");
}

__global__ void zero_s_kernel() {
    g_s[threadIdx.x] = 0.0f;
}

// ---------------- fused avgpool: img -> img2, img4, img8 ----------------
__global__ void pool_kernel(const float* __restrict__ x) {
    int gid = blockIdx.x * blockDim.x + threadIdx.x;
    int t  = gid >> 12;
    int p  = gid & 4095;
    int ph = p >> 6;
    int pw = p & 63;

    const float* base = x + (size_t)t * HW1 + (size_t)(ph * 8) * D1 + pw * 8;

    float s2[4][4];
#pragma unroll
    for (int r2 = 0; r2 < 4; r2++) {
        float4 a0 = *(const float4*)(base + (size_t)(2 * r2) * D1);
        float4 b0 = *(const float4*)(base + (size_t)(2 * r2) * D1 + 4);
        float4 a1 = *(const float4*)(base + (size_t)(2 * r2 + 1) * D1);
        float4 b1 = *(const float4*)(base + (size_t)(2 * r2 + 1) * D1 + 4);
        s2[r2][0] = (a0.x + a0.y + a1.x + a1.y) * 0.25f;
        s2[r2][1] = (a0.z + a0.w + a1.z + a1.w) * 0.25f;
        s2[r2][2] = (b0.x + b0.y + b1.x + b1.y) * 0.25f;
        s2[r2][3] = (b0.z + b0.w + b1.z + b1.w) * 0.25f;
    }

    float* o2 = g_img2 + (size_t)t * HW2;
#pragma unroll
    for (int r2 = 0; r2 < 4; r2++) {
        float4 v = make_float4(s2[r2][0], s2[r2][1], s2[r2][2], s2[r2][3]);
        *(float4*)(o2 + (size_t)(ph * 4 + r2) * 256 + pw * 4) = v;
    }

    float s4[2][2];
#pragma unroll
    for (int r4 = 0; r4 < 2; r4++)
#pragma unroll
        for (int c4 = 0; c4 < 2; c4++)
            s4[r4][c4] = (s2[2*r4][2*c4] + s2[2*r4][2*c4+1]
                        + s2[2*r4+1][2*c4] + s2[2*r4+1][2*c4+1]) * 0.25f;

    float* o4 = g_img4 + (size_t)t * HW4;
#pragma unroll
    for (int r4 = 0; r4 < 2; r4++) {
        float2 v = make_float2(s4[r4][0], s4[r4][1]);
        *(float2*)(o4 + (size_t)(ph * 2 + r4) * 128 + pw * 2) = v;
    }

    g_img8[(size_t)t * HW8 + (size_t)ph * 64 + pw] =
        (s4[0][0] + s4[0][1] + s4[1][0] + s4[1][1]) * 0.25f;
}

// ---------------- fused affine_grid + grid_sample + dot with Wk ----------------
template<int DIM>
__global__ void sample_dot_kernel(const float* __restrict__ img,
                                  const float* __restrict__ theta,
                                  const float* __restrict__ Wk,
                                  float* __restrict__ xreg,
                                  int level) {
    constexpr int LOG = (DIM == 512) ? 9 : (DIM == 256) ? 8 : (DIM == 128) ? 7 : 6;
    const int t   = blockIdx.y;
    const int tid = blockIdx.x * blockDim.x + threadIdx.x;   // 0..HW/4-1
    const int w   = tid & (DIM - 1);
    const int h0  = (tid >> LOG) << 2;

    const float* th = theta + t * 6;
    const float th0 = __ldg(th + 0), th1 = __ldg(th + 1), th2 = __ldg(th + 2);
    const float th3 = __ldg(th + 3), th4 = __ldg(th + 4), th5 = __ldg(th + 5);

    constexpr float inv  = 2.0f / (float)DIM;
    constexpr float half = 0.5f * (float)DIM;
    const float xn  = ((float)w  + 0.5f) * inv - 1.0f;
    const float yn0 = ((float)h0 + 0.5f) * inv - 1.0f;
    const float gx0 = fmaf(th0, xn, fmaf(th1, yn0, th2));
    const float gy0 = fmaf(th3, xn, fmaf(th4, yn0, th5));
    const float ix0 = fmaf(gx0 + 1.0f, half, -0.5f);
    const float iy0 = fmaf(gy0 + 1.0f, half, -0.5f);
    const float ix3 = fmaf(3.0f, th1, ix0);
    const float iy3 = fmaf(3.0f, th4, iy0);

    const float* base = img + (size_t)t * (DIM * DIM);
    const size_t obase = (size_t)t * (DIM * DIM) + (size_t)h0 * DIM + w;

    const bool interior =
        fminf(ix0, ix3) >= 0.0f && fmaxf(ix0, ix3) < (float)(DIM - 1) &&
        fminf(iy0, iy3) >= 0.0f && fmaxf(iy0, iy3) < (float)(DIM - 1);

    float c = 0.0f;
    if (interior) {
#pragma unroll
        for (int j = 0; j < 4; j++) {
            const float ix = fmaf((float)j, th1, ix0);
            const float iy = fmaf((float)j, th4, iy0);
            const float fx = floorf(ix), fy = floorf(iy);
            const int x0 = (int)fx, y0 = (int)fy;
            const float wx = ix - fx, wy = iy - fy;

            const float* r0 = base + (size_t)y0 * DIM + x0;
            const float* r1 = r0 + DIM;
            const float v00 = __ldg(r0);
            const float v01 = __ldg(r0 + 1);
            const float v10 = __ldg(r1);
            const float v11 = __ldg(r1 + 1);

            const float top = fmaf(v01, wx, v00 * (1.0f - wx));
            const float bot = fmaf(v11, wx, v10 * (1.0f - wx));
            const float val = fmaf(bot, wy, top * (1.0f - wy));
            st_cs(xreg + obase + (size_t)j * DIM, val);
            c = fmaf(val, __ldg(Wk + (h0 + j) * DIM + w), c);
        }
    } else {
#pragma unroll
        for (int j = 0; j < 4; j++) {
            const float ix = fmaf((float)j, th1, ix0);
            const float iy = fmaf((float)j, th4, iy0);
            const float fx = floorf(ix), fy = floorf(iy);
            const int x0 = (int)fx, y0 = (int)fy;
            const float wx = ix - fx, wy = iy - fy;

            const bool x0v = (unsigned)x0       < (unsigned)DIM;
            const bool x1v = (unsigned)(x0 + 1) < (unsigned)DIM;
            const bool y0v = (unsigned)y0       < (unsigned)DIM;
            const bool y1v = (unsigned)(y0 + 1) < (unsigned)DIM;

            const int x0c = min(max(x0, 0), DIM - 1);
            const int x1c = min(max(x0 + 1, 0), DIM - 1);
            const int y0c = min(max(y0, 0), DIM - 1);
            const int y1c = min(max(y0 + 1, 0), DIM - 1);

            const float* r0 = base + (size_t)y0c * DIM;
            const float* r1 = base + (size_t)y1c * DIM;
            const float v00 = __ldg(r0 + x0c);
            const float v01 = __ldg(r0 + x1c);
            const float v10 = __ldg(r1 + x0c);
            const float v11 = __ldg(r1 + x1c);

            const float wx1 = x1v ? wx : 0.0f;
            const float wx0 = x0v ? (1.0f - wx) : 0.0f;
            const float wy1 = y1v ? wy : 0.0f;
            const float wy0 = y0v ? (1.0f - wy) : 0.0f;

            const float top = fmaf(v01, wx1, v00 * wx0);
            const float bot = fmaf(v11, wx1, v10 * wx0);
            const float val = fmaf(bot, wy1, top * wy0);
            st_cs(xreg + obase + (size_t)j * DIM, val);
            c = fmaf(val, __ldg(Wk + (h0 + j) * DIM + w), c);
        }
    }

#pragma unroll
    for (int o = 16; o; o >>= 1)
        c += __shfl_down_sync(0xffffffffu, c, o);

    __shared__ float sm[8];
    const int lane = threadIdx.x & 31;
    const int wrp  = threadIdx.x >> 5;
    if (lane == 0) sm[wrp] = c;
    __syncthreads();
    if (wrp == 0) {
        float v = (lane < 8) ? sm[lane] : 0.0f;
#pragma unroll
        for (int o = 4; o; o >>= 1)
            v += __shfl_down_sync(0xffffffffu, v, o);
        if (lane == 0) atomicAdd(&g_s[level * TT + t], v);
    }
}

// ---------------- rank-1 outer product: L[t,:] = s[t] * Wk ----------------
__global__ void outer_kernel(const float* __restrict__ Wk,
                             float* __restrict__ L,
                             int level, int hw4) {
    int t = blockIdx.y;
    int i = blockIdx.x * blockDim.x + threadIdx.x;
    float sv = g_s[level * TT + t];
    float4 wv = __ldg((const float4*)Wk + i);
    float4 o = make_float4(sv * wv.x, sv * wv.y, sv * wv.z, sv * wv.w);
    st_cs4((float*)((float4*)L + (size_t)t * hw4 + i), o);
}

extern "C" void kernel_launch(void* const* d_in, const int* in_sizes, int n_in,
                              void* d_out, int out_size) {
    const float* x     = (const float*)d_in[0];
    const float* theta = (const float*)d_in[1];
    const float* W1    = (const float*)d_in[2];
    const float* W2    = (const float*)d_in[3];
    const float* W4    = (const float*)d_in[4];
    const float* W8    = (const float*)d_in[5];
    float* out = (float*)d_out;

    size_t off = 0;
    float* xr1 = out + off; off += (size_t)TT * HW1;
    float* L1  = out + off; off += (size_t)TT * HW1;
    float* xr2 = out + off; off += (size_t)TT * HW2;
    float* L2  = out + off; off += (size_t)TT * HW2;
    float* xr4 = out + off; off += (size_t)TT * HW4;
    float* L4  = out + off; off += (size_t)TT * HW4;
    float* xr8 = out + off; off += (size_t)TT * HW8;
    float* L8  = out + off; off += (size_t)TT * HW8;

    void *p2, *p4, *p8;
    cudaGetSymbolAddress(&p2, g_img2);
    cudaGetSymbolAddress(&p4, g_img4);
    cudaGetSymbolAddress(&p8, g_img8);
    const float* i2 = (const float*)p2;
    const float* i4 = (const float*)p4;
    const float* i8 = (const float*)p8;

    // One-time creation of side streams/events (host resources, not device
    // memory; created on the eager correctness call, reused during capture).
    static cudaStream_t s1 = nullptr, s2 = nullptr;
    static cudaEvent_t e0 = nullptr, ep = nullptr, e1 = nullptr, e2 = nullptr;
    if (s1 == nullptr) {
        cudaStreamCreateWithFlags(&s1, cudaStreamNonBlocking);
        cudaStreamCreateWithFlags(&s2, cudaStreamNonBlocking);
        cudaEventCreateWithFlags(&e0, cudaEventDisableTiming);
        cudaEventCreateWithFlags(&ep, cudaEventDisableTiming);
        cudaEventCreateWithFlags(&e1, cudaEventDisableTiming);
        cudaEventCreateWithFlags(&e2, cudaEventDisableTiming);
    }
    cudaStream_t s0 = 0;   // legacy default stream (the captured stream)

    // s0: zero accumulators, fork
    zero_s_kernel<<<1, 4 * TT, 0, s0>>>();
    cudaEventRecord(e0, s0);

    // s1: level-0 chain (depends only on x + zero_s)
    cudaStreamWaitEvent(s1, e0, 0);
    sample_dot_kernel<512><<<dim3(HW1 / 1024, TT), 256, 0, s1>>>(x, theta, W1, xr1, 0);
    outer_kernel<<<dim3(HW1 / 1024, TT), 256, 0, s1>>>(W1, L1, 0, HW1 / 4);
    cudaEventRecord(e1, s1);

    // s0: pool, then level-1 chain
    pool_kernel<<<(TT * 4096) / 256, 256, 0, s0>>>(x);
    cudaEventRecord(ep, s0);

    // s2: small levels (need pool; ep implies zero_s since same stream)
    cudaStreamWaitEvent(s2, ep, 0);
    sample_dot_kernel<128><<<dim3(HW4 / 1024, TT), 256, 0, s2>>>(i4, theta, W4, xr4, 2);
    outer_kernel<<<dim3(HW4 / 1024, TT), 256, 0, s2>>>(W4, L4, 2, HW4 / 4);
    sample_dot_kernel< 64><<<dim3(HW8 / 1024, TT), 256, 0, s2>>>(i8, theta, W8, xr8, 3);
    outer_kernel<<<dim3(HW8 / 1024, TT), 256, 0, s2>>>(W8, L8, 3, HW8 / 4);
    cudaEventRecord(e2, s2);

    // s0: level-1 chain
    sample_dot_kernel<256><<<dim3(HW2 / 1024, TT), 256, 0, s0>>>(i2, theta, W2, xr2, 1);
    outer_kernel<<<dim3(HW2 / 1024, TT), 256, 0, s0>>>(W2, L2, 1, HW2 / 4);

    // join everything back to s0
    cudaStreamWaitEvent(s0, e1, 0);
    cudaStreamWaitEvent(s0, e2, 0);
}

// round 5
// speedup vs baseline: 2.2626x; 1.1352x over previous
#include <cuda_runtime.h>

// ---------------- problem constants ----------------
#define TT 256
#define D1 512
#define HW1 (512*512)
#define HW2 (256*256)
#define HW4 (128*128)
#define HW8 (64*64)

// ---------------- device scratch (no allocations allowed) ----------------
__device__ float g_img2[(size_t)TT * HW2];
__device__ float g_img4[(size_t)TT * HW4];
__device__ float g_img8[(size_t)TT * HW8];
__device__ float g_s[4 * TT];

__device__ __forceinline__ void st_cs(float* p, float v) {
    asm volatile("st.global.cs.f32 [%0], %1;" :: "l"(p), "f"(v) : "memory");
}
__device__ __forceinline__ void st_cs4(float* p, float4 v) {
    asm volatile("st.global.cs.v4.f32 [%0], {%1,%2,%3,%4};"
                 :: "l"(p), "f"(v.x), "f"(v.y), "f"(v.z), "f"(v.w) : "memory");
}

__global__ void zero_s_kernel() {
    g_s[threadIdx.x] = 0.0f;
}

// ---------------- fused: avgpool pyramid + affine sample + dot (level 0) --------
// Block = one 64-wide x 16-high tile of image t.
//   Phase A: pool the tile -> img2 (32x8), img4 (16x4), img8 (8x2). The tile
//            load warms L1 for the gathers (theta ~= identity).
//   Phase B: each thread samples a 4-high column of output pixels and
//            accumulates the dot with W1.
__global__ void fused512_kernel(const float* __restrict__ x,
                                const float* __restrict__ theta,
                                const float* __restrict__ Wk,
                                float* __restrict__ xreg) {
    const int t  = blockIdx.y;
    const int tx = blockIdx.x & 7;    // 8 tiles across (64 px each)
    const int ty = blockIdx.x >> 3;   // 32 tiles down (16 px each)

    const float* base = x + (size_t)t * HW1;

    // ---------- Phase A: pooling ----------
    __shared__ float p2[8][32];
    __shared__ float p4[4][16];
    {
        const int qx = threadIdx.x & 31;   // quad col within tile (32 quads)
        const int qy = threadIdx.x >> 5;   // quad row within tile (8 quads)
        const int gx = tx * 64 + qx * 2;
        const int gy = ty * 16 + qy * 2;
        const float2 a = *(const float2*)(base + (size_t)gy * D1 + gx);
        const float2 b = *(const float2*)(base + (size_t)(gy + 1) * D1 + gx);
        const float v2 = (a.x + a.y + b.x + b.y) * 0.25f;
        p2[qy][qx] = v2;
        st_cs(g_img2 + (size_t)t * HW2 + (size_t)(ty * 8 + qy) * 256 + tx * 32 + qx, v2);
    }
    __syncthreads();
    if (threadIdx.x < 64) {
        const int ix = threadIdx.x & 15;
        const int iy = threadIdx.x >> 4;
        const float v4 = (p2[2*iy][2*ix] + p2[2*iy][2*ix+1]
                        + p2[2*iy+1][2*ix] + p2[2*iy+1][2*ix+1]) * 0.25f;
        p4[iy][ix] = v4;
        st_cs(g_img4 + (size_t)t * HW4 + (size_t)(ty * 4 + iy) * 128 + tx * 16 + ix, v4);
    }
    __syncthreads();
    if (threadIdx.x < 16) {
        const int ix = threadIdx.x & 7;
        const int iy = threadIdx.x >> 3;
        const float v8 = (p4[2*iy][2*ix] + p4[2*iy][2*ix+1]
                        + p4[2*iy+1][2*ix] + p4[2*iy+1][2*ix+1]) * 0.25f;
        st_cs(g_img8 + (size_t)t * HW8 + (size_t)(ty * 2 + iy) * 64 + tx * 8 + ix, v8);
    }

    // ---------- Phase B: affine sample + dot ----------
    const int w  = tx * 64 + (threadIdx.x & 63);
    const int h0 = ty * 16 + (threadIdx.x >> 6) * 4;

    const float* th = theta + t * 6;
    const float th0 = __ldg(th + 0), th1 = __ldg(th + 1), th2 = __ldg(th + 2);
    const float th3 = __ldg(th + 3), th4 = __ldg(th + 4), th5 = __ldg(th + 5);

    constexpr float inv  = 2.0f / 512.0f;
    constexpr float half = 256.0f;
    const float xn  = ((float)w  + 0.5f) * inv - 1.0f;
    const float yn0 = ((float)h0 + 0.5f) * inv - 1.0f;
    const float gx0 = fmaf(th0, xn, fmaf(th1, yn0, th2));
    const float gy0 = fmaf(th3, xn, fmaf(th4, yn0, th5));
    const float ix0 = fmaf(gx0 + 1.0f, half, -0.5f);
    const float iy0 = fmaf(gy0 + 1.0f, half, -0.5f);
    const float ix3 = fmaf(3.0f, th1, ix0);
    const float iy3 = fmaf(3.0f, th4, iy0);

    const size_t obase = (size_t)t * HW1 + (size_t)h0 * D1 + w;

    const bool interior =
        fminf(ix0, ix3) >= 0.0f && fmaxf(ix0, ix3) < 511.0f &&
        fminf(iy0, iy3) >= 0.0f && fmaxf(iy0, iy3) < 511.0f;

    float c = 0.0f;
    if (interior) {
#pragma unroll
        for (int j = 0; j < 4; j++) {
            const float ix = fmaf((float)j, th1, ix0);
            const float iy = fmaf((float)j, th4, iy0);
            const float fx = floorf(ix), fy = floorf(iy);
            const int x0 = (int)fx, y0 = (int)fy;
            const float wx = ix - fx, wy = iy - fy;

            const float* r0 = base + (size_t)y0 * D1 + x0;
            const float* r1 = r0 + D1;
            const float v00 = __ldg(r0);
            const float v01 = __ldg(r0 + 1);
            const float v10 = __ldg(r1);
            const float v11 = __ldg(r1 + 1);

            const float top = fmaf(v01, wx, v00 * (1.0f - wx));
            const float bot = fmaf(v11, wx, v10 * (1.0f - wx));
            const float val = fmaf(bot, wy, top * (1.0f - wy));
            st_cs(xreg + obase + (size_t)j * D1, val);
            c = fmaf(val, __ldg(Wk + (h0 + j) * D1 + w), c);
        }
    } else {
#pragma unroll
        for (int j = 0; j < 4; j++) {
            const float ix = fmaf((float)j, th1, ix0);
            const float iy = fmaf((float)j, th4, iy0);
            const float fx = floorf(ix), fy = floorf(iy);
            const int x0 = (int)fx, y0 = (int)fy;
            const float wx = ix - fx, wy = iy - fy;

            const bool x0v = (unsigned)x0       < 512u;
            const bool x1v = (unsigned)(x0 + 1) < 512u;
            const bool y0v = (unsigned)y0       < 512u;
            const bool y1v = (unsigned)(y0 + 1) < 512u;

            const int x0c = min(max(x0, 0), 511);
            const int x1c = min(max(x0 + 1, 0), 511);
            const int y0c = min(max(y0, 0), 511);
            const int y1c = min(max(y0 + 1, 0), 511);

            const float* r0 = base + (size_t)y0c * D1;
            const float* r1 = base + (size_t)y1c * D1;
            const float v00 = __ldg(r0 + x0c);
            const float v01 = __ldg(r0 + x1c);
            const float v10 = __ldg(r1 + x0c);
            const float v11 = __ldg(r1 + x1c);

            const float wx1 = x1v ? wx : 0.0f;
            const float wx0 = x0v ? (1.0f - wx) : 0.0f;
            const float wy1 = y1v ? wy : 0.0f;
            const float wy0 = y0v ? (1.0f - wy) : 0.0f;

            const float top = fmaf(v01, wx1, v00 * wx0);
            const float bot = fmaf(v11, wx1, v10 * wx0);
            const float val = fmaf(bot, wy1, top * wy0);
            st_cs(xreg + obase + (size_t)j * D1, val);
            c = fmaf(val, __ldg(Wk + (h0 + j) * D1 + w), c);
        }
    }

#pragma unroll
    for (int o = 16; o; o >>= 1)
        c += __shfl_down_sync(0xffffffffu, c, o);

    __shared__ float sm[8];
    const int lane = threadIdx.x & 31;
    const int wrp  = threadIdx.x >> 5;
    if (lane == 0) sm[wrp] = c;
    __syncthreads();
    if (wrp == 0) {
        float v = (lane < 8) ? sm[lane] : 0.0f;
#pragma unroll
        for (int o = 4; o; o >>= 1)
            v += __shfl_down_sync(0xffffffffu, v, o);
        if (lane == 0) atomicAdd(&g_s[t], v);
    }
}

// ---------------- affine sample + dot for the pooled levels ----------------
template<int DIM>
__global__ void sample_dot_kernel(const float* __restrict__ img,
                                  const float* __restrict__ theta,
                                  const float* __restrict__ Wk,
                                  float* __restrict__ xreg,
                                  int level) {
    constexpr int LOG = (DIM == 512) ? 9 : (DIM == 256) ? 8 : (DIM == 128) ? 7 : 6;
    const int t   = blockIdx.y;
    const int tid = blockIdx.x * blockDim.x + threadIdx.x;
    const int w   = tid & (DIM - 1);
    const int h0  = (tid >> LOG) << 2;

    const float* th = theta + t * 6;
    const float th0 = __ldg(th + 0), th1 = __ldg(th + 1), th2 = __ldg(th + 2);
    const float th3 = __ldg(th + 3), th4 = __ldg(th + 4), th5 = __ldg(th + 5);

    constexpr float inv  = 2.0f / (float)DIM;
    constexpr float half = 0.5f * (float)DIM;
    const float xn  = ((float)w  + 0.5f) * inv - 1.0f;
    const float yn0 = ((float)h0 + 0.5f) * inv - 1.0f;
    const float gx0 = fmaf(th0, xn, fmaf(th1, yn0, th2));
    const float gy0 = fmaf(th3, xn, fmaf(th4, yn0, th5));
    const float ix0 = fmaf(gx0 + 1.0f, half, -0.5f);
    const float iy0 = fmaf(gy0 + 1.0f, half, -0.5f);
    const float ix3 = fmaf(3.0f, th1, ix0);
    const float iy3 = fmaf(3.0f, th4, iy0);

    const float* base = img + (size_t)t * (DIM * DIM);
    const size_t obase = (size_t)t * (DIM * DIM) + (size_t)h0 * DIM + w;

    const bool interior =
        fminf(ix0, ix3) >= 0.0f && fmaxf(ix0, ix3) < (float)(DIM - 1) &&
        fminf(iy0, iy3) >= 0.0f && fmaxf(iy0, iy3) < (float)(DIM - 1);

    float c = 0.0f;
    if (interior) {
#pragma unroll
        for (int j = 0; j < 4; j++) {
            const float ix = fmaf((float)j, th1, ix0);
            const float iy = fmaf((float)j, th4, iy0);
            const float fx = floorf(ix), fy = floorf(iy);
            const int x0 = (int)fx, y0 = (int)fy;
            const float wx = ix - fx, wy = iy - fy;

            const float* r0 = base + (size_t)y0 * DIM + x0;
            const float* r1 = r0 + DIM;
            const float v00 = __ldg(r0);
            const float v01 = __ldg(r0 + 1);
            const float v10 = __ldg(r1);
            const float v11 = __ldg(r1 + 1);

            const float top = fmaf(v01, wx, v00 * (1.0f - wx));
            const float bot = fmaf(v11, wx, v10 * (1.0f - wx));
            const float val = fmaf(bot, wy, top * (1.0f - wy));
            st_cs(xreg + obase + (size_t)j * DIM, val);
            c = fmaf(val, __ldg(Wk + (h0 + j) * DIM + w), c);
        }
    } else {
#pragma unroll
        for (int j = 0; j < 4; j++) {
            const float ix = fmaf((float)j, th1, ix0);
            const float iy = fmaf((float)j, th4, iy0);
            const float fx = floorf(ix), fy = floorf(iy);
            const int x0 = (int)fx, y0 = (int)fy;
            const float wx = ix - fx, wy = iy - fy;

            const bool x0v = (unsigned)x0       < (unsigned)DIM;
            const bool x1v = (unsigned)(x0 + 1) < (unsigned)DIM;
            const bool y0v = (unsigned)y0       < (unsigned)DIM;
            const bool y1v = (unsigned)(y0 + 1) < (unsigned)DIM;

            const int x0c = min(max(x0, 0), DIM - 1);
            const int x1c = min(max(x0 + 1, 0), DIM - 1);
            const int y0c = min(max(y0, 0), DIM - 1);
            const int y1c = min(max(y0 + 1, 0), DIM - 1);

            const float* r0 = base + (size_t)y0c * DIM;
            const float* r1 = base + (size_t)y1c * DIM;
            const float v00 = __ldg(r0 + x0c);
            const float v01 = __ldg(r0 + x1c);
            const float v10 = __ldg(r1 + x0c);
            const float v11 = __ldg(r1 + x1c);

            const float wx1 = x1v ? wx : 0.0f;
            const float wx0 = x0v ? (1.0f - wx) : 0.0f;
            const float wy1 = y1v ? wy : 0.0f;
            const float wy0 = y0v ? (1.0f - wy) : 0.0f;

            const float top = fmaf(v01, wx1, v00 * wx0);
            const float bot = fmaf(v11, wx1, v10 * wx0);
            const float val = fmaf(bot, wy1, top * wy0);
            st_cs(xreg + obase + (size_t)j * DIM, val);
            c = fmaf(val, __ldg(Wk + (h0 + j) * DIM + w), c);
        }
    }

#pragma unroll
    for (int o = 16; o; o >>= 1)
        c += __shfl_down_sync(0xffffffffu, c, o);

    __shared__ float sm[8];
    const int lane = threadIdx.x & 31;
    const int wrp  = threadIdx.x >> 5;
    if (lane == 0) sm[wrp] = c;
    __syncthreads();
    if (wrp == 0) {
        float v = (lane < 8) ? sm[lane] : 0.0f;
#pragma unroll
        for (int o = 4; o; o >>= 1)
            v += __shfl_down_sync(0xffffffffu, v, o);
        if (lane == 0) atomicAdd(&g_s[level * TT + t], v);
    }
}

// ---------------- rank-1 outer product: L[t,:] = s[t] * Wk ----------------
__global__ void outer_kernel(const float* __restrict__ Wk,
                             float* __restrict__ L,
                             int level, int hw4) {
    int t = blockIdx.y;
    int i = blockIdx.x * blockDim.x + threadIdx.x;
    float sv = g_s[level * TT + t];
    float4 wv = __ldg((const float4*)Wk + i);
    float4 o = make_float4(sv * wv.x, sv * wv.y, sv * wv.z, sv * wv.w);
    st_cs4((float*)((float4*)L + (size_t)t * hw4 + i), o);
}

extern "C" void kernel_launch(void* const* d_in, const int* in_sizes, int n_in,
                              void* d_out, int out_size) {
    const float* x     = (const float*)d_in[0];
    const float* theta = (const float*)d_in[1];
    const float* W1    = (const float*)d_in[2];
    const float* W2    = (const float*)d_in[3];
    const float* W4    = (const float*)d_in[4];
    const float* W8    = (const float*)d_in[5];
    float* out = (float*)d_out;

    size_t off = 0;
    float* xr1 = out + off; off += (size_t)TT * HW1;
    float* L1  = out + off; off += (size_t)TT * HW1;
    float* xr2 = out + off; off += (size_t)TT * HW2;
    float* L2  = out + off; off += (size_t)TT * HW2;
    float* xr4 = out + off; off += (size_t)TT * HW4;
    float* L4  = out + off; off += (size_t)TT * HW4;
    float* xr8 = out + off; off += (size_t)TT * HW8;
    float* L8  = out + off; off += (size_t)TT * HW8;

    void *p2, *p4, *p8;
    cudaGetSymbolAddress(&p2, g_img2);
    cudaGetSymbolAddress(&p4, g_img4);
    cudaGetSymbolAddress(&p8, g_img8);
    const float* i2 = (const float*)p2;
    const float* i4 = (const float*)p4;
    const float* i8 = (const float*)p8;

    static cudaStream_t s1 = nullptr, s2 = nullptr;
    static cudaEvent_t ef = nullptr, e1 = nullptr, e2 = nullptr;
    if (s1 == nullptr) {
        cudaStreamCreateWithFlags(&s1, cudaStreamNonBlocking);
        cudaStreamCreateWithFlags(&s2, cudaStreamNonBlocking);
        cudaEventCreateWithFlags(&ef, cudaEventDisableTiming);
        cudaEventCreateWithFlags(&e1, cudaEventDisableTiming);
        cudaEventCreateWithFlags(&e2, cudaEventDisableTiming);
    }
    cudaStream_t s0 = 0;

    // serial head: zero accumulators, fused level-0 (pool + sample + dot)
    zero_s_kernel<<<1, 4 * TT, 0, s0>>>();
    fused512_kernel<<<dim3(256, TT), 256, 0, s0>>>(x, theta, W1, xr1);
    cudaEventRecord(ef, s0);

    // fork: outer1 (pure writes) on s1
    cudaStreamWaitEvent(s1, ef, 0);
    outer_kernel<<<dim3(HW1 / 1024, TT), 256, 0, s1>>>(W1, L1, 0, HW1 / 4);
    cudaEventRecord(e1, s1);

    // small levels on s2
    cudaStreamWaitEvent(s2, ef, 0);
    sample_dot_kernel<128><<<dim3(HW4 / 1024, TT), 256, 0, s2>>>(i4, theta, W4, xr4, 2);
    outer_kernel<<<dim3(HW4 / 1024, TT), 256, 0, s2>>>(W4, L4, 2, HW4 / 4);
    sample_dot_kernel< 64><<<dim3(HW8 / 1024, TT), 256, 0, s2>>>(i8, theta, W8, xr8, 3);
    outer_kernel<<<dim3(HW8 / 1024, TT), 256, 0, s2>>>(W8, L8, 3, HW8 / 4);
    cudaEventRecord(e2, s2);

    // level-1 chain on s0 (overlaps outer1 + smalls)
    sample_dot_kernel<256><<<dim3(HW2 / 1024, TT), 256, 0, s0>>>(i2, theta, W2, xr2, 1);
    outer_kernel<<<dim3(HW2 / 1024, TT), 256, 0, s0>>>(W2, L2, 1, HW2 / 4);

    // join
    cudaStreamWaitEvent(s0, e1, 0);
    cudaStreamWaitEvent(s0, e2, 0);
}

// round 6
// speedup vs baseline: 2.2809x; 1.0081x over previous
#include <cuda_runtime.h>

// ---------------- problem constants ----------------
#define TT 256
#define D1 512
#define HW1 (512*512)
#define HW2 (256*256)
#define HW4 (128*128)
#define HW8 (64*64)

// ---------------- device scratch (no allocations allowed) ----------------
__device__ float g_img2[(size_t)TT * HW2];
__device__ float g_img4[(size_t)TT * HW4];
__device__ float g_img8[(size_t)TT * HW8];
__device__ float g_s[4 * TT];

__device__ __forceinline__ void st_cs(float* p, float v) {
    asm volatile("st.global.cs.f32 [%0], %1;" :: "l"(p), "f"(v) : "memory");
}
__device__ __forceinline__ void st_cs4(float* p, float4 v) {
    asm volatile("st.global.cs.v4.f32 [%0], {%1,%2,%3,%4};"
                 :: "l"(p), "f"(v.x), "f"(v.y), "f"(v.z), "f"(v.w) : "memory");
}

__global__ void zero_s_kernel() {
    g_s[threadIdx.x] = 0.0f;
}

// ============ shared sampling core: gather-then-compute, 4-high column ============
template<int DIM>
__device__ __forceinline__ void sample_column(
    const float* __restrict__ base, const float* __restrict__ Wk,
    float* __restrict__ xreg, size_t obase,
    int w, int h0,
    float th0, float th1, float th2, float th3, float th4, float th5,
    float& c)
{
    constexpr float inv  = 2.0f / (float)DIM;
    constexpr float half = 0.5f * (float)DIM;
    const float xn  = ((float)w  + 0.5f) * inv - 1.0f;
    const float yn0 = ((float)h0 + 0.5f) * inv - 1.0f;
    const float gx0 = fmaf(th0, xn, fmaf(th1, yn0, th2));
    const float gy0 = fmaf(th3, xn, fmaf(th4, yn0, th5));
    const float ix0 = fmaf(gx0 + 1.0f, half, -0.5f);
    const float iy0 = fmaf(gy0 + 1.0f, half, -0.5f);
    const float ix3 = fmaf(3.0f, th1, ix0);
    const float iy3 = fmaf(3.0f, th4, iy0);

    const bool interior =
        fminf(ix0, ix3) >= 0.0f && fmaxf(ix0, ix3) < (float)(DIM - 1) &&
        fminf(iy0, iy3) >= 0.0f && fmaxf(iy0, iy3) < (float)(DIM - 1);

    float v00[4], v01[4], v10[4], v11[4], wxs[4], wys[4], wk[4];

    if (interior) {
        // phase 1: issue all gathers (independent -> front-batched by ptxas)
#pragma unroll
        for (int j = 0; j < 4; j++) {
            const float ix = fmaf((float)j, th1, ix0);
            const float iy = fmaf((float)j, th4, iy0);
            const float fx = floorf(ix), fy = floorf(iy);
            const int x0 = (int)fx, y0 = (int)fy;
            wxs[j] = ix - fx; wys[j] = iy - fy;
            const float* r0 = base + (size_t)y0 * DIM + x0;
            const float* r1 = r0 + DIM;
            v00[j] = __ldg(r0);
            v01[j] = __ldg(r0 + 1);
            v10[j] = __ldg(r1);
            v11[j] = __ldg(r1 + 1);
            wk[j]  = __ldg(Wk + (h0 + j) * DIM + w);
        }
        // phase 2: compute + store
#pragma unroll
        for (int j = 0; j < 4; j++) {
            const float wx = wxs[j], wy = wys[j];
            const float top = fmaf(v01[j], wx, v00[j] * (1.0f - wx));
            const float bot = fmaf(v11[j], wx, v10[j] * (1.0f - wx));
            const float val = fmaf(bot, wy, top * (1.0f - wy));
            st_cs(xreg + obase + (size_t)j * DIM, val);
            c = fmaf(val, wk[j], c);
        }
    } else {
#pragma unroll
        for (int j = 0; j < 4; j++) {
            const float ix = fmaf((float)j, th1, ix0);
            const float iy = fmaf((float)j, th4, iy0);
            const float fx = floorf(ix), fy = floorf(iy);
            const int x0 = (int)fx, y0 = (int)fy;
            const float wx = ix - fx, wy = iy - fy;

            const bool x0v = (unsigned)x0       < (unsigned)DIM;
            const bool x1v = (unsigned)(x0 + 1) < (unsigned)DIM;
            const bool y0v = (unsigned)y0       < (unsigned)DIM;
            const bool y1v = (unsigned)(y0 + 1) < (unsigned)DIM;

            const int x0c = min(max(x0, 0), DIM - 1);
            const int x1c = min(max(x0 + 1, 0), DIM - 1);
            const int y0c = min(max(y0, 0), DIM - 1);
            const int y1c = min(max(y0 + 1, 0), DIM - 1);

            const float* r0 = base + (size_t)y0c * DIM;
            const float* r1 = base + (size_t)y1c * DIM;
            const float a00 = __ldg(r0 + x0c);
            const float a01 = __ldg(r0 + x1c);
            const float a10 = __ldg(r1 + x0c);
            const float a11 = __ldg(r1 + x1c);

            const float wx1 = x1v ? wx : 0.0f;
            const float wx0 = x0v ? (1.0f - wx) : 0.0f;
            const float wy1 = y1v ? wy : 0.0f;
            const float wy0 = y0v ? (1.0f - wy) : 0.0f;

            const float top = fmaf(a01, wx1, a00 * wx0);
            const float bot = fmaf(a11, wx1, a10 * wx0);
            const float val = fmaf(bot, wy1, top * wy0);
            st_cs(xreg + obase + (size_t)j * DIM, val);
            c = fmaf(val, __ldg(Wk + (h0 + j) * DIM + w), c);
        }
    }
}

__device__ __forceinline__ void block_reduce_dot(float c, float* slot) {
#pragma unroll
    for (int o = 16; o; o >>= 1)
        c += __shfl_down_sync(0xffffffffu, c, o);
    __shared__ float sm[8];
    const int lane = threadIdx.x & 31;
    const int wrp  = threadIdx.x >> 5;
    if (lane == 0) sm[wrp] = c;
    __syncthreads();
    if (wrp == 0) {
        float v = (lane < 8) ? sm[lane] : 0.0f;
#pragma unroll
        for (int o = 4; o; o >>= 1)
            v += __shfl_down_sync(0xffffffffu, v, o);
        if (lane == 0) atomicAdd(slot, v);
    }
}

// ---------------- fused: avgpool pyramid + affine sample + dot (level 0) --------
__global__ void fused512_kernel(const float* __restrict__ x,
                                const float* __restrict__ theta,
                                const float* __restrict__ Wk,
                                float* __restrict__ xreg) {
    const int t  = blockIdx.y;
    const int tx = blockIdx.x & 7;    // 8 tiles across (64 px)
    const int ty = blockIdx.x >> 3;   // 32 tiles down (16 px)

    const float* base = x + (size_t)t * HW1;

    // ---------- Phase A: pooling (pyramid stores KEEP L2 residency) ----------
    __shared__ float p2[8][32];
    __shared__ float p4[4][16];
    {
        const int qx = threadIdx.x & 31;
        const int qy = threadIdx.x >> 5;
        const int gx = tx * 64 + qx * 2;
        const int gy = ty * 16 + qy * 2;
        const float2 a = *(const float2*)(base + (size_t)gy * D1 + gx);
        const float2 b = *(const float2*)(base + (size_t)(gy + 1) * D1 + gx);
        const float v2 = (a.x + a.y + b.x + b.y) * 0.25f;
        p2[qy][qx] = v2;
        g_img2[(size_t)t * HW2 + (size_t)(ty * 8 + qy) * 256 + tx * 32 + qx] = v2;
    }
    __syncthreads();
    if (threadIdx.x < 64) {
        const int ix = threadIdx.x & 15;
        const int iy = threadIdx.x >> 4;
        const float v4 = (p2[2*iy][2*ix] + p2[2*iy][2*ix+1]
                        + p2[2*iy+1][2*ix] + p2[2*iy+1][2*ix+1]) * 0.25f;
        p4[iy][ix] = v4;
        g_img4[(size_t)t * HW4 + (size_t)(ty * 4 + iy) * 128 + tx * 16 + ix] = v4;
    }
    __syncthreads();
    if (threadIdx.x < 16) {
        const int ix = threadIdx.x & 7;
        const int iy = threadIdx.x >> 3;
        const float v8 = (p4[2*iy][2*ix] + p4[2*iy][2*ix+1]
                        + p4[2*iy+1][2*ix] + p4[2*iy+1][2*ix+1]) * 0.25f;
        g_img8[(size_t)t * HW8 + (size_t)(ty * 2 + iy) * 64 + tx * 8 + ix] = v8;
    }

    // ---------- Phase B: affine sample + dot ----------
    const int w  = tx * 64 + (threadIdx.x & 63);
    const int h0 = ty * 16 + (threadIdx.x >> 6) * 4;

    const float* th = theta + t * 6;
    const float th0 = __ldg(th + 0), th1 = __ldg(th + 1), th2 = __ldg(th + 2);
    const float th3 = __ldg(th + 3), th4 = __ldg(th + 4), th5 = __ldg(th + 5);

    const size_t obase = (size_t)t * HW1 + (size_t)h0 * D1 + w;

    float c = 0.0f;
    sample_column<512>(base, Wk, xreg, obase, w, h0, th0, th1, th2, th3, th4, th5, c);
    block_reduce_dot(c, &g_s[t]);
}

// ---------------- affine sample + dot for the pooled levels ----------------
template<int DIM>
__global__ void sample_dot_kernel(const float* __restrict__ img,
                                  const float* __restrict__ theta,
                                  const float* __restrict__ Wk,
                                  float* __restrict__ xreg,
                                  int level) {
    constexpr int LOG = (DIM == 512) ? 9 : (DIM == 256) ? 8 : (DIM == 128) ? 7 : 6;
    const int t   = blockIdx.y;
    const int tid = blockIdx.x * blockDim.x + threadIdx.x;
    const int w   = tid & (DIM - 1);
    const int h0  = (tid >> LOG) << 2;

    const float* th = theta + t * 6;
    const float th0 = __ldg(th + 0), th1 = __ldg(th + 1), th2 = __ldg(th + 2);
    const float th3 = __ldg(th + 3), th4 = __ldg(th + 4), th5 = __ldg(th + 5);

    const float* base = img + (size_t)t * (DIM * DIM);
    const size_t obase = (size_t)t * (DIM * DIM) + (size_t)h0 * DIM + w;

    float c = 0.0f;
    sample_column<DIM>(base, Wk, xreg, obase, w, h0, th0, th1, th2, th3, th4, th5, c);
    block_reduce_dot(c, &g_s[level * TT + t]);
}

// ---------------- rank-1 outer product: L[t,:] = s[t] * Wk ----------------
__global__ void outer_kernel(const float* __restrict__ Wk,
                             float* __restrict__ L,
                             int level, int hw4) {
    int t = blockIdx.y;
    int i = blockIdx.x * blockDim.x + threadIdx.x;
    float sv = g_s[level * TT + t];
    float4 wv = __ldg((const float4*)Wk + i);
    float4 o = make_float4(sv * wv.x, sv * wv.y, sv * wv.z, sv * wv.w);
    st_cs4((float*)((float4*)L + (size_t)t * hw4 + i), o);
}

extern "C" void kernel_launch(void* const* d_in, const int* in_sizes, int n_in,
                              void* d_out, int out_size) {
    const float* x     = (const float*)d_in[0];
    const float* theta = (const float*)d_in[1];
    const float* W1    = (const float*)d_in[2];
    const float* W2    = (const float*)d_in[3];
    const float* W4    = (const float*)d_in[4];
    const float* W8    = (const float*)d_in[5];
    float* out = (float*)d_out;

    size_t off = 0;
    float* xr1 = out + off; off += (size_t)TT * HW1;
    float* L1  = out + off; off += (size_t)TT * HW1;
    float* xr2 = out + off; off += (size_t)TT * HW2;
    float* L2  = out + off; off += (size_t)TT * HW2;
    float* xr4 = out + off; off += (size_t)TT * HW4;
    float* L4  = out + off; off += (size_t)TT * HW4;
    float* xr8 = out + off; off += (size_t)TT * HW8;
    float* L8  = out + off; off += (size_t)TT * HW8;

    void *p2, *p4, *p8;
    cudaGetSymbolAddress(&p2, g_img2);
    cudaGetSymbolAddress(&p4, g_img4);
    cudaGetSymbolAddress(&p8, g_img8);
    const float* i2 = (const float*)p2;
    const float* i4 = (const float*)p4;
    const float* i8 = (const float*)p8;

    static cudaStream_t s1 = nullptr, s2 = nullptr;
    static cudaEvent_t ef = nullptr, e1 = nullptr, e2 = nullptr;
    if (s1 == nullptr) {
        cudaStreamCreateWithFlags(&s1, cudaStreamNonBlocking);
        cudaStreamCreateWithFlags(&s2, cudaStreamNonBlocking);
        cudaEventCreateWithFlags(&ef, cudaEventDisableTiming);
        cudaEventCreateWithFlags(&e1, cudaEventDisableTiming);
        cudaEventCreateWithFlags(&e2, cudaEventDisableTiming);
    }
    cudaStream_t s0 = 0;

    // serial head
    zero_s_kernel<<<1, 4 * TT, 0, s0>>>();
    fused512_kernel<<<dim3(256, TT), 256, 0, s0>>>(x, theta, W1, xr1);
    cudaEventRecord(ef, s0);

    // fork: outer1 (pure writes) on s1
    cudaStreamWaitEvent(s1, ef, 0);
    outer_kernel<<<dim3(HW1 / 1024, TT), 256, 0, s1>>>(W1, L1, 0, HW1 / 4);
    cudaEventRecord(e1, s1);

    // small levels on s2
    cudaStreamWaitEvent(s2, ef, 0);
    sample_dot_kernel<128><<<dim3(HW4 / 1024, TT), 256, 0, s2>>>(i4, theta, W4, xr4, 2);
    outer_kernel<<<dim3(HW4 / 1024, TT), 256, 0, s2>>>(W4, L4, 2, HW4 / 4);
    sample_dot_kernel< 64><<<dim3(HW8 / 1024, TT), 256, 0, s2>>>(i8, theta, W8, xr8, 3);
    outer_kernel<<<dim3(HW8 / 1024, TT), 256, 0, s2>>>(W8, L8, 3, HW8 / 4);
    cudaEventRecord(e2, s2);

    // level-1 chain on s0
    sample_dot_kernel<256><<<dim3(HW2 / 1024, TT), 256, 0, s0>>>(i2, theta, W2, xr2, 1);
    outer_kernel<<<dim3(HW2 / 1024, TT), 256, 0, s0>>>(W2, L2, 1, HW2 / 4);

    // join
    cudaStreamWaitEvent(s0, e1, 0);
    cudaStreamWaitEvent(s0, e2, 0);
}